// round 15
// baseline (speedup 1.0000x reference)
#include <cuda_runtime.h>

#define Bb 4
#define Cc 64
#define Hh 256
#define Ww 256
#define Nn (Hh*Ww)
#define NPAIRS 12
#define HALF_S 512
#define MAXS 1024
#define NFEAT (NPAIRS*Cc*MAXS)

#define TILE_R 2          // interior rows per block
#define NG (Ww/4)         // 64 column groups of 4
#define PREP_T 128        // threads per prep block
#define ROWS_BLK (Hh/TILE_R)   // 128 row-blocks per image

__device__ unsigned char g_code[Bb*Nn];   // per pixel: lab | (pd<<4)
__device__ int g_idx[NPAIRS*MAXS];

__device__ __forceinline__ unsigned argmax4(float4 v0, float4 v1, float4 v2, float4 v3) {
    unsigned packed = 0;
    {   float a=v0.x; int bi=0;
        if (v1.x>a){a=v1.x;bi=1;} if (v2.x>a){a=v2.x;bi=2;} if (v3.x>a){a=v3.x;bi=3;}
        packed |= (unsigned)bi; }
    {   float a=v0.y; int bi=0;
        if (v1.y>a){a=v1.y;bi=1;} if (v2.y>a){a=v2.y;bi=2;} if (v3.y>a){a=v3.y;bi=3;}
        packed |= (unsigned)bi << 8; }
    {   float a=v0.z; int bi=0;
        if (v1.z>a){a=v1.z;bi=1;} if (v2.z>a){a=v2.z;bi=2;} if (v3.z>a){a=v3.z;bi=3;}
        packed |= (unsigned)bi << 16; }
    {   float a=v0.w; int bi=0;
        if (v1.w>a){a=v1.w;bi=1;} if (v2.w>a){a=v2.w;bi=2;} if (v3.w>a){a=v3.w;bi=3;}
        packed |= (unsigned)bi << 24; }
    return packed;
}

// ------- fused: argmax (vec4, 2 tasks/thread, loads front-batched incl.
//         pass-2 labels) -> 3x3 max-dilate (SIMD bytes) -> pack --------------
__global__ void __launch_bounds__(PREP_T)
k_prep(const float* __restrict__ preds, const int* __restrict__ labels) {
    // grid: Bb * ROWS_BLK = 512 blocks, 128 threads
    int blk = blockIdx.x;
    int b = blk >> 7;                        // / ROWS_BLK
    int ty0 = (blk & (ROWS_BLK-1)) * TILE_R; // first interior row
    int tid = threadIdx.x;

    __shared__ unsigned spred[TILE_R+2][NG]; // packed argmax bytes

    const float* pb = preds + (size_t)b * 4 * Nn;

    // pass-2 task for this thread (always valid: 128 tasks, 128 threads)
    int r2 = tid >> 6;
    int cg2 = tid & (NG-1);
    int off2 = ((ty0 + r2)*Ww)/4 + cg2;

    // pass 1: 256 argmax tasks, 2 per thread. Front-batch ALL loads (8 pred
    // float4 + 1 label int4) so 9 independent loads are in flight together.
    int task0 = tid, task1 = tid + PREP_T;
    int r0 = task0 >> 6, cg0t = task0 & (NG-1);
    int r1 = task1 >> 6, cg1t = task1 & (NG-1);
    int y0 = ty0 - 1 + r0;
    int y1 = ty0 - 1 + r1;
    bool ok0 = (y0 >= 0 && y0 < Hh);
    bool ok1 = (y1 >= 0 && y1 < Hh);
    int off0 = (y0*Ww)/4 + cg0t;
    int off1 = (y1*Ww)/4 + cg1t;

    int4 lab = ((const int4*)(labels + (size_t)b*Nn))[off2];   // prefetch
    float4 a0, a1, a2, a3, b0, b1, b2, b3;
    if (ok0) {
        a0 = ((const float4*)pb)[off0];
        a1 = ((const float4*)(pb + Nn))[off0];
        a2 = ((const float4*)(pb + 2*Nn))[off0];
        a3 = ((const float4*)(pb + 3*Nn))[off0];
    }
    if (ok1) {
        b0 = ((const float4*)pb)[off1];
        b1 = ((const float4*)(pb + Nn))[off1];
        b2 = ((const float4*)(pb + 2*Nn))[off1];
        b3 = ((const float4*)(pb + 3*Nn))[off1];
    }
    spred[r0][cg0t] = ok0 ? argmax4(a0, a1, a2, a3) : 0u;
    spred[r1][cg1t] = ok1 ? argmax4(b0, b1, b2, b3) : 0u;
    __syncthreads();

    // pass 2: dilate + merge prefetched labels (1 task per thread)
    {
        int rr = r2 + 1;
        unsigned m = 0;
#pragma unroll
        for (int d = -1; d <= 1; d++) {
            unsigned w = spred[rr+d][cg2];
            unsigned lb = (cg2 > 0)    ? (spred[rr+d][cg2-1] >> 24) : 0u;
            unsigned rb = (cg2 < NG-1) ? (spred[rr+d][cg2+1] & 0xffu) : 0u;
            unsigned wl = (w << 8) | lb;
            unsigned wr = (w >> 8) | (rb << 24);
            m = __vmaxu4(m, __vmaxu4(w, __vmaxu4(wl, wr)));
        }
        unsigned lab4 = (unsigned)lab.x | ((unsigned)lab.y << 8) |
                        ((unsigned)lab.z << 16) | ((unsigned)lab.w << 24);
        ((unsigned*)(g_code + (size_t)b*Nn))[off2] = lab4 | (m << 4);
    }
}

// ---------------- selection: one block per (b,cls) pair ----------------------
// hard rank r -> slot r (r<1024); easy rank e -> slot 512+max(totH-512,0)+e (<1024)
__global__ void __launch_bounds__(1024)
k_select(float* __restrict__ out) {
    int pair = blockIdx.x;
    int b = pair / 3;
    int cls = pair % 3 + 1;
    int tid = threadIdx.x;
    g_idx[pair*MAXS + tid] = -1;
    if (tid == 0) out[NFEAT + pair] = (float)cls;   // label tail

    const uint4* codes = (const uint4*)(g_code + b*Nn) + tid*4;
    uint4 q0 = codes[0], q1 = codes[1], q2 = codes[2], q3 = codes[3];
    unsigned w[16] = { q0.x,q0.y,q0.z,q0.w, q1.x,q1.y,q1.z,q1.w,
                       q2.x,q2.y,q2.z,q2.w, q3.x,q3.y,q3.z,q3.w };
    const unsigned clsL = (unsigned)cls * 0x01010101u;
    const unsigned clsH = (unsigned)cls * 0x10101010u;

    int hbits = 0, ebits = 0;
#pragma unroll
    for (int i = 0; i < 16; i++) {
        unsigned labm = __vcmpeq4(w[i] & 0x0F0F0F0Fu, clsL);
        unsigned pdm  = __vcmpeq4(w[i] & 0xF0F0F0F0u, clsH);
        ebits += __popc(labm & pdm);
        hbits += __popc(labm & ~pdm);
    }
    unsigned long long v = ((unsigned long long)(hbits>>3) << 32) | (unsigned)(ebits>>3);
    unsigned long long own = v;
    int lane = tid & 31, wid = tid >> 5;
#pragma unroll
    for (int o = 1; o < 32; o <<= 1) {
        unsigned long long n = __shfl_up_sync(0xffffffffu, v, o);
        if (lane >= o) v += n;
    }
    __shared__ unsigned long long wsum[32];
    __shared__ unsigned long long s_total;
    if (lane == 31) wsum[wid] = v;
    __syncthreads();
    if (wid == 0) {
        unsigned long long ww = wsum[lane];
#pragma unroll
        for (int o = 1; o < 32; o <<= 1) {
            unsigned long long n = __shfl_up_sync(0xffffffffu, ww, o);
            if (lane >= o) ww += n;
        }
        wsum[lane] = ww;
        if (lane == 31) s_total = ww;
    }
    __syncthreads();

    unsigned long long excl = v - own + (wid > 0 ? wsum[wid-1] : 0ULL);
    int hr = (int)(excl >> 32);
    int er = (int)(excl & 0xffffffffULL);
    int totH = (int)(s_total >> 32);
    int excess = totH > HALF_S ? totH - HALF_S : 0;

    int base = tid * 64;
    int* slots = g_idx + pair*MAXS;
#pragma unroll
    for (int i = 0; i < 16; i++) {
        unsigned labm = __vcmpeq4(w[i] & 0x0F0F0F0Fu, clsL);
        if (!labm) continue;
        unsigned pdm = __vcmpeq4(w[i] & 0xF0F0F0F0u, clsH);
#pragma unroll
        for (int k = 0; k < 4; k++) {
            if ((labm >> (k*8)) & 0xffu) {
                int p = base + i*4 + k;
                if ((pdm >> (k*8)) & 0xffu) {
                    int slot = HALF_S + excess + er;
                    if (slot < MAXS) slots[slot] = p;
                    er++;
                } else {
                    if (hr < MAXS) slots[hr] = p;
                    hr++;
                }
            }
        }
    }
}

// ------------- gather: 4 samples per thread, int4 slot load, ldcs -----------
__global__ void k_gather(const float* __restrict__ feat, float* __restrict__ out) {
    int t = blockIdx.x * blockDim.x + threadIdx.x;   // over NFEAT/4
    if (t >= NFEAT/4) return;
    int s4   = t & 255;              // sample group (4 samples)
    int c    = (t >> 8) & (Cc - 1);
    int pair = t >> 14;
    int b = pair / 3;
    int4 s = ((const int4*)(g_idx + pair*MAXS))[s4];
    const float* plane = feat + ((size_t)(b*Cc + c)) * Nn;
    float4 r;
    r.x = (s.x >= 0) ? __ldcs(plane + s.x) : 0.0f;
    r.y = (s.y >= 0) ? __ldcs(plane + s.y) : 0.0f;
    r.z = (s.z >= 0) ? __ldcs(plane + s.z) : 0.0f;
    r.w = (s.w >= 0) ? __ldcs(plane + s.w) : 0.0f;
    ((float4*)out)[t] = r;
}

extern "C" void kernel_launch(void* const* d_in, const int* in_sizes, int n_in,
                              void* d_out, int out_size) {
    const float* feat   = (const float*)d_in[0];  // [4,64,256,256]
    const int*   labels = (const int*)d_in[1];    // [4,256,256]
    const float* preds  = (const float*)d_in[2];  // [4,4,256,256]
    float* out = (float*)d_out;

    k_prep<<<Bb*ROWS_BLK, PREP_T>>>(preds, labels);
    k_select<<<NPAIRS, 1024>>>(out);
    k_gather<<<(NFEAT/4 + 255) / 256, 256>>>(feat, out);
}